// round 9
// baseline (speedup 1.0000x reference)
#include <cuda_runtime.h>

#define N 8192
#define THREADS 256
#define ROWS_PER_CTA 4
#define NUM_BLOCKS (N / ROWS_PER_CTA)              // 2048
#define COLS_PER_THREAD 4
#define ITERS (N / (THREADS * COLS_PER_THREAD))    // 8

typedef unsigned long long ull;
union f2u { float2 f; ull u; };

__device__ float        g_xs[N];
__device__ float        g_ys[N];
__device__ float        g_partials[NUM_BLOCKS];
__device__ unsigned int g_count = 0;

__device__ __forceinline__ ull f2add(ull a, ull b) {
    ull c; asm("add.rn.f32x2 %0, %1, %2;" : "=l"(c) : "l"(a), "l"(b)); return c;
}
__device__ __forceinline__ ull f2mul(ull a, ull b) {
    ull c; asm("mul.rn.f32x2 %0, %1, %2;" : "=l"(c) : "l"(a), "l"(b)); return c;
}
__device__ __forceinline__ ull f2fma(ull a, ull b, ull c) {
    ull d; asm("fma.rn.f32x2 %0, %1, %2, %3;" : "=l"(d) : "l"(a), "l"(b), "l"(c)); return d;
}
__device__ __forceinline__ float fsqrt_a(float x) {
    float r; asm("sqrt.approx.f32 %0, %1;" : "=f"(r) : "f"(x)); return r;
}
__device__ __forceinline__ float frcp_a(float x) {
    float r; asm("rcp.approx.f32 %0, %1;" : "=f"(r) : "f"(x)); return r;
}

__global__ void soa_kernel(const float2* __restrict__ pos2) {
    int i = blockIdx.x * blockDim.x + threadIdx.x;
    float2 p = pos2[i];
    g_xs[i] = p.x;
    g_ys[i] = p.y;
}

__global__ __launch_bounds__(THREADS, 4)
void stress_kernel(const float2* __restrict__ pos2,
                   const float*  __restrict__ dist,
                   float* __restrict__ out) {
    const int row0 = blockIdx.x * ROWS_PER_CTA;

    f2u nx[ROWS_PER_CTA], ny[ROWS_PER_CTA];
    #pragma unroll
    for (int k = 0; k < ROWS_PER_CTA; k++) {
        float2 p = __ldg(&pos2[row0 + k]);
        nx[k].f.x = -p.x; nx[k].f.y = -p.x;
        ny[k].f.x = -p.y; ny[k].f.y = -p.y;
    }

    const float* dr0 = dist + (size_t)row0 * N;
    const float* dr1 = dr0 + N;
    const float* dr2 = dr1 + N;
    const float* dr3 = dr2 + N;

    f2u acc01, acc23;
    acc01.f.x = 0.f; acc01.f.y = 0.f;
    acc23.f.x = 0.f; acc23.f.y = 0.f;

    // branchless per-4 (Montgomery batched reciprocal + masked selects)
    auto grp = [&](const float4& d, ull nxp, ull nyp,
                   const f2u& xa, const f2u& xb, const f2u& ya, const f2u& yb) {
        // safe divisors: zeros replaced by 1 so the whole group stays clean
        float s0 = (d.x != 0.0f) ? d.x : 1.0f;
        float s1 = (d.y != 0.0f) ? d.y : 1.0f;
        float s2 = (d.z != 0.0f) ? d.z : 1.0f;
        float s3 = (d.w != 0.0f) ? d.w : 1.0f;

        // Montgomery: 1 MUFU.RCP for 4 reciprocals
        float p01   = s0 * s1;
        float p012  = p01 * s2;
        float p0123 = p012 * s3;
        float R  = frcp_a(p0123);
        float i3 = p012 * R;  float R3 = R  * s3;
        float i2 = p01  * R3; float R2 = R3 * s2;
        float i1 = s0   * R2; float i0 = s1 * R2;

        // masked inverse and masked -1 (term == 0 where d == 0)
        f2u iv01, iv23, mm01, mm23;
        iv01.f.x = (d.x != 0.0f) ? i0 : 0.0f;
        iv01.f.y = (d.y != 0.0f) ? i1 : 0.0f;
        iv23.f.x = (d.z != 0.0f) ? i2 : 0.0f;
        iv23.f.y = (d.w != 0.0f) ? i3 : 0.0f;
        mm01.f.x = (d.x != 0.0f) ? -1.0f : 0.0f;
        mm01.f.y = (d.y != 0.0f) ? -1.0f : 0.0f;
        mm23.f.x = (d.z != 0.0f) ? -1.0f : 0.0f;
        mm23.f.y = (d.w != 0.0f) ? -1.0f : 0.0f;

        ull dxa = f2add(xa.u, nxp);
        ull dya = f2add(ya.u, nyp);
        ull sqa = f2fma(dya, dya, f2mul(dxa, dxa));
        f2u sa; sa.u = sqa;
        f2u pa; pa.f.x = fsqrt_a(sa.f.x); pa.f.y = fsqrt_a(sa.f.y);
        ull qa = f2fma(pa.u, iv01.u, mm01.u);       // pred/d - 1 (or 0)
        acc01.u = f2fma(qa, qa, acc01.u);

        ull dxb = f2add(xb.u, nxp);
        ull dyb = f2add(yb.u, nyp);
        ull sqb = f2fma(dyb, dyb, f2mul(dxb, dxb));
        f2u sb; sb.u = sqb;
        f2u pb; pb.f.x = fsqrt_a(sb.f.x); pb.f.y = fsqrt_a(sb.f.y);
        ull qb = f2fma(pb.u, iv23.u, mm23.u);
        acc23.u = f2fma(qb, qb, acc23.u);
    };

    // ---- software pipeline: prefetch iteration 0 ----
    int j = threadIdx.x * COLS_PER_THREAD;
    float4 x4 = __ldg(reinterpret_cast<const float4*>(&g_xs[j]));
    float4 y4 = __ldg(reinterpret_cast<const float4*>(&g_ys[j]));
    float4 d0 = __ldcs(reinterpret_cast<const float4*>(dr0 + j));
    float4 d1 = __ldcs(reinterpret_cast<const float4*>(dr1 + j));
    float4 d2 = __ldcs(reinterpret_cast<const float4*>(dr2 + j));
    float4 d3 = __ldcs(reinterpret_cast<const float4*>(dr3 + j));

    #pragma unroll
    for (int it = 0; it < ITERS; it++) {
        float4 px4, py4, e0, e1, e2, e3;
        if (it + 1 < ITERS) {
            const int jn = ((it + 1) * THREADS + threadIdx.x) * COLS_PER_THREAD;
            px4 = __ldg(reinterpret_cast<const float4*>(&g_xs[jn]));
            py4 = __ldg(reinterpret_cast<const float4*>(&g_ys[jn]));
            e0  = __ldcs(reinterpret_cast<const float4*>(dr0 + jn));
            e1  = __ldcs(reinterpret_cast<const float4*>(dr1 + jn));
            e2  = __ldcs(reinterpret_cast<const float4*>(dr2 + jn));
            e3  = __ldcs(reinterpret_cast<const float4*>(dr3 + jn));
        }

        f2u xa, xb, ya, yb;
        xa.f.x = x4.x; xa.f.y = x4.y;  xb.f.x = x4.z; xb.f.y = x4.w;
        ya.f.x = y4.x; ya.f.y = y4.y;  yb.f.x = y4.z; yb.f.y = y4.w;

        grp(d0, nx[0].u, ny[0].u, xa, xb, ya, yb);
        grp(d1, nx[1].u, ny[1].u, xa, xb, ya, yb);
        grp(d2, nx[2].u, ny[2].u, xa, xb, ya, yb);
        grp(d3, nx[3].u, ny[3].u, xa, xb, ya, yb);

        x4 = px4; y4 = py4;
        d0 = e0; d1 = e1; d2 = e2; d3 = e3;
    }

    float acc = (acc01.f.x + acc01.f.y) + (acc23.f.x + acc23.f.y);

    // intra-CTA deterministic reduction
    #pragma unroll
    for (int o = 16; o > 0; o >>= 1)
        acc += __shfl_down_sync(0xffffffffu, acc, o);

    __shared__ float warpsum[THREADS / 32];
    const int lane = threadIdx.x & 31;
    const int wid  = threadIdx.x >> 5;
    if (lane == 0) warpsum[wid] = acc;
    __syncthreads();

    __shared__ bool is_last;
    if (threadIdx.x == 0) {
        float v = 0.0f;
        #pragma unroll
        for (int w = 0; w < THREADS / 32; w++) v += warpsum[w];
        g_partials[blockIdx.x] = v;
        __threadfence();
        unsigned int prev = atomicAdd(&g_count, 1u);
        is_last = (prev == NUM_BLOCKS - 1);
    }
    __syncthreads();

    if (is_last) {
        __shared__ double s[THREADS];
        double t = 0.0;
        const float4* p4 = reinterpret_cast<const float4*>(g_partials);
        #pragma unroll
        for (int k = 0; k < NUM_BLOCKS / THREADS / 4; k++) {
            float4 v = p4[threadIdx.x * (NUM_BLOCKS / THREADS / 4) + k];
            t += (double)v.x + (double)v.y + (double)v.z + (double)v.w;
        }
        s[threadIdx.x] = t;
        __syncthreads();
        #pragma unroll
        for (int o = THREADS / 2; o > 0; o >>= 1) {
            if ((int)threadIdx.x < o) s[threadIdx.x] += s[threadIdx.x + o];
            __syncthreads();
        }
        if (threadIdx.x == 0) {
            out[0] = (float)s[0];
            g_count = 0;                 // reset for next graph replay
        }
    }
}

extern "C" void kernel_launch(void* const* d_in, const int* in_sizes, int n_in,
                              void* d_out, int out_size) {
    const float* a = (const float*)d_in[0];
    const float* b = (const float*)d_in[1];
    const float2* pos2;
    const float*  dist;
    if (in_sizes[0] < in_sizes[1]) { pos2 = (const float2*)a; dist = b; }
    else                           { pos2 = (const float2*)b; dist = a; }

    soa_kernel<<<N / 256, 256>>>(pos2);
    stress_kernel<<<NUM_BLOCKS, THREADS>>>(pos2, dist, (float*)d_out);
}

// round 10
// speedup vs baseline: 1.6502x; 1.6502x over previous
#include <cuda_runtime.h>

#define N 8192
#define THREADS 256
#define ROWS_PER_CTA 4
#define NUM_BLOCKS (N / ROWS_PER_CTA)              // 2048
#define COLS_PER_THREAD 4
#define ITERS (N / (THREADS * COLS_PER_THREAD))    // 8

typedef unsigned long long ull;
union f2u { float2 f; ull u; };

__device__ float        g_xs[N];
__device__ float        g_ys[N];
__device__ float        g_partials[NUM_BLOCKS];
__device__ unsigned int g_count = 0;

__device__ __forceinline__ ull f2add(ull a, ull b) {
    ull c; asm("add.rn.f32x2 %0, %1, %2;" : "=l"(c) : "l"(a), "l"(b)); return c;
}
__device__ __forceinline__ ull f2mul(ull a, ull b) {
    ull c; asm("mul.rn.f32x2 %0, %1, %2;" : "=l"(c) : "l"(a), "l"(b)); return c;
}
__device__ __forceinline__ ull f2fma(ull a, ull b, ull c) {
    ull d; asm("fma.rn.f32x2 %0, %1, %2, %3;" : "=l"(d) : "l"(a), "l"(b), "l"(c)); return d;
}
__device__ __forceinline__ float fsqrt_a(float x) {
    float r; asm("sqrt.approx.f32 %0, %1;" : "=f"(r) : "f"(x)); return r;
}
__device__ __forceinline__ float frcp_a(float x) {
    float r; asm("rcp.approx.f32 %0, %1;" : "=f"(r) : "f"(x)); return r;
}

__global__ void soa_kernel(const float2* __restrict__ pos2) {
    int i = blockIdx.x * blockDim.x + threadIdx.x;
    float2 p = pos2[i];
    g_xs[i] = p.x;
    g_ys[i] = p.y;
}

__global__ __launch_bounds__(THREADS, 5)
void stress_kernel(const float2* __restrict__ pos2,
                   const float*  __restrict__ dist,
                   float* __restrict__ out) {
    const int row0 = blockIdx.x * ROWS_PER_CTA;

    f2u nx[ROWS_PER_CTA], ny[ROWS_PER_CTA];
    #pragma unroll
    for (int k = 0; k < ROWS_PER_CTA; k++) {
        float2 p = __ldg(&pos2[row0 + k]);
        nx[k].f.x = -p.x; nx[k].f.y = -p.x;
        ny[k].f.x = -p.y; ny[k].f.y = -p.y;
    }

    const float* dr0 = dist + (size_t)row0 * N;
    const float* dr1 = dr0 + N;
    const float* dr2 = dr1 + N;
    const float* dr3 = dr2 + N;

    f2u acc01, acc23;
    acc01.f.x = 0.f; acc01.f.y = 0.f;
    acc23.f.x = 0.f; acc23.f.y = 0.f;
    float acc_s = 0.f;

    f2u NEG1; NEG1.f.x = -1.f; NEG1.f.y = -1.f;

    for (int it = 0; it < ITERS; it++) {
        const int j = (it * THREADS + threadIdx.x) * COLS_PER_THREAD;

        float4 x4 = __ldg(reinterpret_cast<const float4*>(&g_xs[j]));
        float4 y4 = __ldg(reinterpret_cast<const float4*>(&g_ys[j]));

        float4 d0 = __ldcs(reinterpret_cast<const float4*>(dr0 + j));
        float4 d1 = __ldcs(reinterpret_cast<const float4*>(dr1 + j));
        float4 d2 = __ldcs(reinterpret_cast<const float4*>(dr2 + j));
        float4 d3 = __ldcs(reinterpret_cast<const float4*>(dr3 + j));

        float m0 = fminf(fminf(d0.x, d0.y), fminf(d0.z, d0.w));
        float m1 = fminf(fminf(d1.x, d1.y), fminf(d1.z, d1.w));
        float m2 = fminf(fminf(d2.x, d2.y), fminf(d2.z, d2.w));
        float m3 = fminf(fminf(d3.x, d3.y), fminf(d3.z, d3.w));
        float mn = fminf(fminf(m0, m1), fminf(m2, m3));

        if (mn > 0.0f) {
            f2u xa, xb, ya, yb;
            xa.f.x = x4.x; xa.f.y = x4.y;  xb.f.x = x4.z; xb.f.y = x4.w;
            ya.f.x = y4.x; ya.f.y = y4.y;  yb.f.x = y4.z; yb.f.y = y4.w;

            auto grp = [&](const float4& d, ull nxp, ull nyp) {
                // Montgomery batched reciprocal: 1 MUFU.RCP / 4 elems
                float p01   = d.x * d.y;
                float p012  = p01 * d.z;
                float p0123 = p012 * d.w;
                float R  = frcp_a(p0123);
                float i3 = p012 * R;  float R3 = R  * d.w;
                float i2 = p01  * R3; float R2 = R3 * d.z;
                float i1 = d.x  * R2; float i0 = d.y * R2;
                f2u iv01; iv01.f.x = i0; iv01.f.y = i1;
                f2u iv23; iv23.f.x = i2; iv23.f.y = i3;

                ull dxa = f2add(xa.u, nxp);
                ull dya = f2add(ya.u, nyp);
                ull sqa = f2fma(dya, dya, f2mul(dxa, dxa));
                f2u sa; sa.u = sqa;
                f2u pa; pa.f.x = fsqrt_a(sa.f.x); pa.f.y = fsqrt_a(sa.f.y);
                ull qa = f2fma(pa.u, iv01.u, NEG1.u);     // pred/d - 1
                acc01.u = f2fma(qa, qa, acc01.u);

                ull dxb = f2add(xb.u, nxp);
                ull dyb = f2add(yb.u, nyp);
                ull sqb = f2fma(dyb, dyb, f2mul(dxb, dxb));
                f2u sb; sb.u = sqb;
                f2u pb; pb.f.x = fsqrt_a(sb.f.x); pb.f.y = fsqrt_a(sb.f.y);
                ull qb = f2fma(pb.u, iv23.u, NEG1.u);
                acc23.u = f2fma(qb, qb, acc23.u);
            };

            grp(d0, nx[0].u, ny[0].u);
            grp(d1, nx[1].u, ny[1].u);
            grp(d2, nx[2].u, ny[2].u);
            grp(d3, nx[3].u, ny[3].u);
        } else {
            // exact scalar fallback (rare: group contains a zero distance)
            auto safe = [&](float d, float xj, float yj, float px, float py) {
                float dx = xj + px, dy = yj + py;
                float sq = fmaf(dy, dy, dx * dx);
                float pr = fsqrt_a(sq);
                float q  = (pr - d) * frcp_a(d);
                q = (d != 0.0f) ? q : 0.0f;
                acc_s = fmaf(q, q, acc_s);
            };
            const float4 dd[4] = {d0, d1, d2, d3};
            #pragma unroll
            for (int k = 0; k < ROWS_PER_CTA; k++) {
                safe(dd[k].x, x4.x, y4.x, nx[k].f.x, ny[k].f.x);
                safe(dd[k].y, x4.y, y4.y, nx[k].f.x, ny[k].f.x);
                safe(dd[k].z, x4.z, y4.z, nx[k].f.x, ny[k].f.x);
                safe(dd[k].w, x4.w, y4.w, nx[k].f.x, ny[k].f.x);
            }
        }
    }

    float acc = (acc01.f.x + acc01.f.y) + (acc23.f.x + acc23.f.y) + acc_s;

    // intra-CTA deterministic reduction
    #pragma unroll
    for (int o = 16; o > 0; o >>= 1)
        acc += __shfl_down_sync(0xffffffffu, acc, o);

    __shared__ float warpsum[THREADS / 32];
    const int lane = threadIdx.x & 31;
    const int wid  = threadIdx.x >> 5;
    if (lane == 0) warpsum[wid] = acc;
    __syncthreads();

    __shared__ bool is_last;
    if (threadIdx.x == 0) {
        float v = 0.0f;
        #pragma unroll
        for (int w = 0; w < THREADS / 32; w++) v += warpsum[w];
        g_partials[blockIdx.x] = v;
        __threadfence();
        unsigned int prev = atomicAdd(&g_count, 1u);
        is_last = (prev == NUM_BLOCKS - 1);
    }
    __syncthreads();

    if (is_last) {
        __shared__ double s[THREADS];
        double t = 0.0;
        const float4* p4 = reinterpret_cast<const float4*>(g_partials);
        #pragma unroll
        for (int k = 0; k < NUM_BLOCKS / THREADS / 4; k++) {
            float4 v = p4[threadIdx.x * (NUM_BLOCKS / THREADS / 4) + k];
            t += (double)v.x + (double)v.y + (double)v.z + (double)v.w;
        }
        s[threadIdx.x] = t;
        __syncthreads();
        #pragma unroll
        for (int o = THREADS / 2; o > 0; o >>= 1) {
            if ((int)threadIdx.x < o) s[threadIdx.x] += s[threadIdx.x + o];
            __syncthreads();
        }
        if (threadIdx.x == 0) {
            out[0] = (float)s[0];
            g_count = 0;                 // reset for next graph replay
        }
    }
}

extern "C" void kernel_launch(void* const* d_in, const int* in_sizes, int n_in,
                              void* d_out, int out_size) {
    const float* a = (const float*)d_in[0];
    const float* b = (const float*)d_in[1];
    const float2* pos2;
    const float*  dist;
    if (in_sizes[0] < in_sizes[1]) { pos2 = (const float2*)a; dist = b; }
    else                           { pos2 = (const float2*)b; dist = a; }

    soa_kernel<<<N / 256, 256>>>(pos2);
    stress_kernel<<<NUM_BLOCKS, THREADS>>>(pos2, dist, (float*)d_out);
}